// round 6
// baseline (speedup 1.0000x reference)
#include <cuda_runtime.h>
#include <cstdint>
#include <cstddef>

#define BMAX 32768

// ---------------- device scratch (uninitialized globals; no allocations) ----------------
__device__ float g_x[BMAX * 64];              // tanh features of cond MLP
__device__ float g_cond[3 * BMAX * 256];      // [0]=b_mod, [1]=c_mod, [2]=w_scale
__device__ float g_v[BMAX * 256];             // model visible state (0/1 floats)
__device__ float g_h[BMAX * 256];             // h * w_scale
__device__ float g_t[BMAX * 256];             // v @ W scratch for free energy
__device__ float g_WT[256 * 256];             // W transposed: WT[k*256+c] = W[c*256+k]
__device__ float g_P[64 * 768];               // combined cond-param weights, [k][n]
__device__ float g_pb[768];                   // combined cond-param bias
__device__ float g_Wsum[256];                 // W.sum(axis=0)
__device__ float g_part[BMAX / 4];            // block partial sums (2 * B/8)

// ---------------- threefry2x32-20 (exact JAX PRNG) ----------------
__host__ __device__ inline uint32_t rotl32(uint32_t v, int d) {
    return (v << d) | (v >> (32 - d));
}

__host__ __device__ inline void tf2x32(uint32_t k0, uint32_t k1, uint32_t& x0, uint32_t& x1) {
    uint32_t ks2 = k0 ^ k1 ^ 0x1BD11BDAu;
    x0 += k0; x1 += k1;
    x0 += x1; x1 = rotl32(x1, 13); x1 ^= x0;
    x0 += x1; x1 = rotl32(x1, 15); x1 ^= x0;
    x0 += x1; x1 = rotl32(x1, 26); x1 ^= x0;
    x0 += x1; x1 = rotl32(x1,  6); x1 ^= x0;
    x0 += k1;  x1 += ks2 + 1u;
    x0 += x1; x1 = rotl32(x1, 17); x1 ^= x0;
    x0 += x1; x1 = rotl32(x1, 29); x1 ^= x0;
    x0 += x1; x1 = rotl32(x1, 16); x1 ^= x0;
    x0 += x1; x1 = rotl32(x1, 24); x1 ^= x0;
    x0 += ks2; x1 += k0 + 2u;
    x0 += x1; x1 = rotl32(x1, 13); x1 ^= x0;
    x0 += x1; x1 = rotl32(x1, 15); x1 ^= x0;
    x0 += x1; x1 = rotl32(x1, 26); x1 ^= x0;
    x0 += x1; x1 = rotl32(x1,  6); x1 ^= x0;
    x0 += k0;  x1 += k1 + 3u;
    x0 += x1; x1 = rotl32(x1, 17); x1 ^= x0;
    x0 += x1; x1 = rotl32(x1, 29); x1 ^= x0;
    x0 += x1; x1 = rotl32(x1, 16); x1 ^= x0;
    x0 += x1; x1 = rotl32(x1, 24); x1 ^= x0;
    x0 += k1;  x1 += ks2 + 4u;
    x0 += x1; x1 = rotl32(x1, 13); x1 ^= x0;
    x0 += x1; x1 = rotl32(x1, 15); x1 ^= x0;
    x0 += x1; x1 = rotl32(x1, 26); x1 ^= x0;
    x0 += x1; x1 = rotl32(x1,  6); x1 ^= x0;
    x0 += ks2; x1 += k0 + 5u;
}

// JAX uniform at flat index f of an array with n=2*half elements:
// lane i in [0,half) ciphers counts (i, i+half); flat[i]=out0, flat[i+half]=out1.
__device__ inline float tf_uniform(uint32_t k0, uint32_t k1, uint32_t f, uint32_t half) {
    uint32_t sec = (f >= half) ? 1u : 0u;
    uint32_t lane = sec ? (f - half) : f;
    uint32_t x0 = lane, x1 = lane + half;
    tf2x32(k0, k1, x0, x1);
    uint32_t bits = sec ? x1 : x0;
    return __uint_as_float((bits >> 9) | 0x3f800000u) - 1.0f;
}

__device__ inline float sigmoidf_(float x) {
    float e = expf(-fabsf(x));
    float s = 1.0f / (1.0f + e);
    return (x >= 0.0f) ? s : (1.0f - s);
}

__device__ inline float softplusf_(float x) {
    return fmaxf(x, 0.0f) + log1pf(expf(-fabsf(x)));
}

// ---------------- prep: WT, Wsum, combined cond-param weights ----------------
__global__ void __launch_bounds__(256) prep_kernel(
    const float* __restrict__ W, const float* __restrict__ b, const float* __restrict__ c,
    const float* __restrict__ fc2w, const float* __restrict__ fc2b,
    float* __restrict__ WT, float* __restrict__ P, float* __restrict__ pb,
    float* __restrict__ Wsum)
{
    int idx = blockIdx.x * blockDim.x + threadIdx.x;
    int stride = gridDim.x * blockDim.x;
    for (int i = idx; i < 256 * 256; i += stride) {
        int k = i >> 8, cc = i & 255;
        WT[k * 256 + cc] = W[cc * 256 + k];
    }
    for (int i = idx; i < 64 * 768; i += stride) {
        int k = i / 768, n = i % 768;
        float val;
        if (n < 256)      val = b[n] * fc2w[n * 64 + k] + fc2w[(256 + n) * 64 + k];
        else if (n < 512) { int j = n - 256; val = c[j] * fc2w[(512 + j) * 64 + k] + fc2w[(768 + j) * 64 + k]; }
        else              { int j = n - 512; val = fc2w[(1024 + j) * 64 + k]; }
        P[k * 768 + n] = val;
    }
    for (int i = idx; i < 768; i += stride) {
        float val;
        if (i < 256)      val = b[i] * (1.0f + fc2b[i]) + fc2b[256 + i];
        else if (i < 512) { int j = i - 256; val = c[j] * (1.0f + fc2b[512 + j]) + fc2b[768 + j]; }
        else              { int j = i - 512; val = fc2b[1024 + j]; }
        pb[i] = val;
    }
    for (int i = idx; i < 256; i += stride) {
        float s = 0.0f;
        for (int rr = 0; rr < 256; rr++) s += W[rr * 256 + i];
        Wsum[i] = s;
    }
}

// ---------------- x = tanh(cond @ fc1_w.T + fc1_b), [B,64]x[64,64] ----------------
__global__ void __launch_bounds__(256) cond_fc1_kernel(
    const float* __restrict__ cond, const float* __restrict__ fc1w,
    const float* __restrict__ fc1b, float* __restrict__ xout)
{
    __shared__ float Cs[64][65];
    __shared__ float Ws[64][65];   // Ws[k][j] = fc1w[j*64+k]
    int t = threadIdx.x;
    int r0 = blockIdx.x * 64;
#pragma unroll
    for (int l = 0; l < 4; l++) {
        int id = t + l * 256;
        int j = id >> 4, k4 = (id & 15) << 2;
        float4 w = *(const float4*)(fc1w + j * 64 + k4);
        Ws[k4 + 0][j] = w.x; Ws[k4 + 1][j] = w.y; Ws[k4 + 2][j] = w.z; Ws[k4 + 3][j] = w.w;
    }
#pragma unroll
    for (int l = 0; l < 4; l++) {
        int id = t + l * 256;
        int i = id >> 4, k4 = (id & 15) << 2;
        float4 v = *(const float4*)(cond + (size_t)(r0 + i) * 64 + k4);
        Cs[i][k4 + 0] = v.x; Cs[i][k4 + 1] = v.y; Cs[i][k4 + 2] = v.z; Cs[i][k4 + 3] = v.w;
    }
    __syncthreads();
    int tx = t & 15, ty = t >> 4;
    float acc[4][4];
#pragma unroll
    for (int i = 0; i < 4; i++)
#pragma unroll
        for (int j = 0; j < 4; j++) acc[i][j] = 0.0f;
#pragma unroll 8
    for (int k = 0; k < 64; k++) {
        float a[4], bv[4];
#pragma unroll
        for (int i = 0; i < 4; i++) a[i] = Cs[ty * 4 + i][k];
#pragma unroll
        for (int j = 0; j < 4; j++) bv[j] = Ws[k][tx * 4 + j];
#pragma unroll
        for (int i = 0; i < 4; i++)
#pragma unroll
            for (int j = 0; j < 4; j++) acc[i][j] = fmaf(a[i], bv[j], acc[i][j]);
    }
#pragma unroll
    for (int i = 0; i < 4; i++) {
        int r = r0 + ty * 4 + i;
#pragma unroll
        for (int j = 0; j < 4; j++) {
            int jj = tx * 4 + j;
            xout[(size_t)r * 64 + jj] = tanhf(acc[i][j] + fc1b[jj]);
        }
    }
}

// ---------------- v_model init: noise rows (threefry) + copy of v_data ----------------
__global__ void __launch_bounds__(256) init_v_kernel(
    const float* __restrict__ vdata, float* __restrict__ v,
    int B, int n_noise, uint32_t k0, uint32_t k1)
{
    int total = B * 256;
    uint32_t half = (uint32_t)(n_noise * 128);
    for (int idx = blockIdx.x * blockDim.x + threadIdx.x; idx < total;
         idx += gridDim.x * blockDim.x) {
        int r = idx >> 8;
        float val;
        if (r < n_noise) {
            float u = tf_uniform(k0, k1, (uint32_t)idx, half);
            val = (u < 0.5f) ? 1.0f : 0.0f;
        } else {
            val = vdata[idx];
        }
        v[idx] = val;
    }
}

// ---------------- generic 128x128x16 SGEMM with fused epilogues ----------------
// MODE 0: cond params: out base = g_cond; val=acc+pb[c]; c<256->b_mod, <512->c_mod,
//         else w_scale=1+0.05*tanh(val). N=768.
// MODE 1: h-sample: p=sigmoid(acc*ws+cmod); u=uniform(k1,f); out = (u<p)?ws:0  (stores h*w_scale)
// MODE 2: v-sample: p=sigmoid(acc+bmod);    u=uniform(k2,f); out = (u<p)?1:0
// MODE 3: plain store (v @ W for free energy)
template <int MODE>
__global__ void __launch_bounds__(256, 2) sgemm_kernel(
    const float* __restrict__ A, const float* __restrict__ Bm,
    float* __restrict__ out,
    const float* __restrict__ e0, const float* __restrict__ e1,
    int M, int N, int K,
    uint32_t rk0, uint32_t rk1, uint32_t half)
{
    __shared__ float As[16][132];
    __shared__ float Bs[16][128];
    const int t = threadIdx.x;
    const int tx = t & 15, ty = t >> 4;
    const int bx = blockIdx.x, by = blockIdx.y;
    const float* Ab = A + (size_t)by * 128 * K;
    const float* Bb = Bm + (size_t)bx * 128;

    float acc[8][8];
#pragma unroll
    for (int i = 0; i < 8; i++)
#pragma unroll
        for (int j = 0; j < 8; j++) acc[i][j] = 0.0f;

    for (int kb = 0; kb < K; kb += 16) {
#pragma unroll
        for (int l = 0; l < 2; l++) {
            int id = t + l * 256;
            int row = id >> 2;
            int c4 = (id & 3) << 2;
            float4 va = *(const float4*)(Ab + (size_t)row * K + kb + c4);
            As[c4 + 0][row] = va.x; As[c4 + 1][row] = va.y;
            As[c4 + 2][row] = va.z; As[c4 + 3][row] = va.w;
        }
#pragma unroll
        for (int l = 0; l < 2; l++) {
            int id = t + l * 256;
            int kk = id >> 5;
            int n4 = (id & 31) << 2;
            *(float4*)&Bs[kk][n4] = *(const float4*)(Bb + (size_t)(kb + kk) * N + n4);
        }
        __syncthreads();
#pragma unroll
        for (int kk = 0; kk < 16; kk++) {
            float a[8], bv[8];
#pragma unroll
            for (int i = 0; i < 8; i++) a[i] = As[kk][ty * 8 + i];
#pragma unroll
            for (int j = 0; j < 8; j++) bv[j] = Bs[kk][tx * 8 + j];
#pragma unroll
            for (int i = 0; i < 8; i++)
#pragma unroll
                for (int j = 0; j < 8; j++) acc[i][j] = fmaf(a[i], bv[j], acc[i][j]);
        }
        __syncthreads();
    }

#pragma unroll
    for (int i = 0; i < 8; i++) {
        int r = by * 128 + ty * 8 + i;
#pragma unroll
        for (int j = 0; j < 8; j++) {
            int c = bx * 128 + tx * 8 + j;
            float v = acc[i][j];
            if (MODE == 0) {
                float val = v + e0[c];
                if (c >= 512) val = 1.0f + 0.05f * tanhf(val);
                size_t idx = (size_t)(c >> 8) * M * 256 + (size_t)r * 256 + (c & 255);
                out[idx] = val;
            } else if (MODE == 1) {
                size_t idx = (size_t)r * 256 + c;
                float ws = e0[idx];
                float p = sigmoidf_(fmaf(v, ws, e1[idx]));
                float u = tf_uniform(rk0, rk1, (uint32_t)idx, half);
                out[idx] = (u < p) ? ws : 0.0f;
            } else if (MODE == 2) {
                size_t idx = (size_t)r * 256 + c;
                float p = sigmoidf_(v + e0[idx]);
                float u = tf_uniform(rk0, rk1, (uint32_t)idx, half);
                out[idx] = (u < p) ? 1.0f : 0.0f;
            } else {
                out[(size_t)r * 256 + c] = v;
            }
        }
    }
}

// ---------------- free-energy row reduce (deterministic) ----------------
__global__ void __launch_bounds__(256) fe_reduce_kernel(
    const float* __restrict__ vw, const float* __restrict__ v,
    const float* __restrict__ bmod, const float* __restrict__ cmod,
    const float* __restrict__ ws, const float* __restrict__ Wsum,
    float sign, float* __restrict__ part, int partBase)
{
    __shared__ float sW[256];
    __shared__ float wres[8];
    int t = threadIdx.x;
    sW[t] = Wsum[t];
    __syncthreads();
    int warp = t >> 5, lane = t & 31;
    int r = blockIdx.x * 8 + warp;
    size_t base = (size_t)r * 256;
    float s2v = 0.0f, s2f = 0.0f, s1v = 0.0f, s1f = 0.0f;
#pragma unroll
    for (int jj = 0; jj < 8; jj++) {
        int c = jj * 32 + lane;
        float tt = vw[base + c];
        float w  = ws[base + c];
        float cm = cmod[base + c];
        float tv = tt * w;
        float lv = tv + cm;
        float lf = fmaf(sW[c], w, cm) - tv;
        s2v += softplusf_(lv);
        s2f += softplusf_(lf);
        float bm = bmod[base + c];
        float vv = v[base + c];
        s1v = fmaf(vv, bm, s1v);
        s1f = fmaf(1.0f - vv, bm, s1f);
    }
#pragma unroll
    for (int o = 16; o > 0; o >>= 1) {
        s2v += __shfl_xor_sync(0xffffffffu, s2v, o);
        s2f += __shfl_xor_sync(0xffffffffu, s2f, o);
        s1v += __shfl_xor_sync(0xffffffffu, s1v, o);
        s1f += __shfl_xor_sync(0xffffffffu, s1f, o);
    }
    if (lane == 0) {
        float av = s1v + s2v;       // = -fe_v
        float af = s1f + s2f;       // = -fe_f
        float mx = fmaxf(av, af);
        float fe = -(mx + log1pf(expf(-fabsf(av - af))));
        wres[warp] = sign * fe;
    }
    __syncthreads();
    if (t == 0) {
        float s = 0.0f;
#pragma unroll
        for (int w = 0; w < 8; w++) s += wres[w];
        part[partBase + blockIdx.x] = s;
    }
}

__global__ void __launch_bounds__(256) final_reduce_kernel(
    const float* __restrict__ part, int n, float invB, float* __restrict__ out)
{
    __shared__ float s[256];
    float acc = 0.0f;
    for (int i = threadIdx.x; i < n; i += 256) acc += part[i];
    s[threadIdx.x] = acc;
    __syncthreads();
    for (int o = 128; o > 0; o >>= 1) {
        if (threadIdx.x < o) s[threadIdx.x] += s[threadIdx.x + o];
        __syncthreads();
    }
    if (threadIdx.x == 0) out[0] = s[0] * invB;
}

// ---------------- host: JAX key chain ----------------
static inline void host_split2(uint32_t k0, uint32_t k1, uint32_t* ka, uint32_t* kb) {
    uint32_t a0 = 0, b0 = 2; tf2x32(k0, k1, a0, b0);
    uint32_t a1 = 1, b1 = 3; tf2x32(k0, k1, a1, b1);
    ka[0] = a0; ka[1] = a1; kb[0] = b0; kb[1] = b1;
}
static inline void host_split3(uint32_t k0, uint32_t k1,
                               uint32_t* kA, uint32_t* kB, uint32_t* kC) {
    uint32_t a0 = 0, b0 = 3; tf2x32(k0, k1, a0, b0);
    uint32_t a1 = 1, b1 = 4; tf2x32(k0, k1, a1, b1);
    uint32_t a2 = 2, b2 = 5; tf2x32(k0, k1, a2, b2);
    kA[0] = a0; kA[1] = a1;
    kB[0] = a2; kB[1] = b0;
    kC[0] = b1; kC[1] = b2;
}

extern "C" void kernel_launch(void* const* d_in, const int* in_sizes, int n_in,
                              void* d_out, int out_size)
{
    const float* v_data = (const float*)d_in[0];
    const float* cond   = (const float*)d_in[1];
    const float* W      = (const float*)d_in[2];
    const float* b      = (const float*)d_in[3];
    const float* c      = (const float*)d_in[4];
    const float* fc1w   = (const float*)d_in[5];
    const float* fc1b   = (const float*)d_in[6];
    const float* fc2w   = (const float*)d_in[7];
    const float* fc2b   = (const float*)d_in[8];

    int B = in_sizes[0] / 256;
    if (B > BMAX) B = BMAX;
    int n_noise = (int)((double)B * 0.1);   // int(B*0.1) => 3276 for B=32768

    float *p_x, *p_cond, *p_v, *p_h, *p_t, *p_WT, *p_P, *p_pb, *p_Wsum, *p_part;
    cudaGetSymbolAddress((void**)&p_x,    g_x);
    cudaGetSymbolAddress((void**)&p_cond, g_cond);
    cudaGetSymbolAddress((void**)&p_v,    g_v);
    cudaGetSymbolAddress((void**)&p_h,    g_h);
    cudaGetSymbolAddress((void**)&p_t,    g_t);
    cudaGetSymbolAddress((void**)&p_WT,   g_WT);
    cudaGetSymbolAddress((void**)&p_P,    g_P);
    cudaGetSymbolAddress((void**)&p_pb,   g_pb);
    cudaGetSymbolAddress((void**)&p_Wsum, g_Wsum);
    cudaGetSymbolAddress((void**)&p_part, g_part);
    float* p_bmod = p_cond;
    float* p_cmod = p_cond + (size_t)B * 256;
    float* p_ws   = p_cond + (size_t)2 * B * 256;

    // JAX key chain: key(42) -> split(2) -> 5x split(3)
    uint32_t rng[2] = {0u, 42u};
    uint32_t kn[2];
    host_split2(rng[0], rng[1], rng, kn);
    uint32_t k1s[5][2], k2s[5][2];
    for (int s = 0; s < 5; s++) {
        uint32_t nk[2];
        host_split3(rng[0], rng[1], nk, k1s[s], k2s[s]);
        rng[0] = nk[0]; rng[1] = nk[1];
    }

    prep_kernel<<<128, 256>>>(W, b, c, fc2w, fc2b, p_WT, p_P, p_pb, p_Wsum);
    cond_fc1_kernel<<<B / 64, 256>>>(cond, fc1w, fc1b, p_x);

    dim3 g0(6, B / 128);
    sgemm_kernel<0><<<g0, 256>>>(p_x, p_P, p_cond, p_pb, nullptr,
                                 B, 768, 64, 0u, 0u, 0u);

    init_v_kernel<<<2048, 256>>>(v_data, p_v, B, n_noise, kn[0], kn[1]);

    uint32_t half = (uint32_t)B * 128u;
    dim3 g1(2, B / 128);
    for (int s = 0; s < 5; s++) {
        sgemm_kernel<1><<<g1, 256>>>(p_v, W, p_h, p_ws, p_cmod,
                                     B, 256, 256, k1s[s][0], k1s[s][1], half);
        sgemm_kernel<2><<<g1, 256>>>(p_h, p_WT, p_v, p_bmod, nullptr,
                                     B, 256, 256, k2s[s][0], k2s[s][1], half);
    }

    // free energy: data (+) and model (-)
    sgemm_kernel<3><<<g1, 256>>>(v_data, W, p_t, nullptr, nullptr,
                                 B, 256, 256, 0u, 0u, 0u);
    fe_reduce_kernel<<<B / 8, 256>>>(p_t, v_data, p_bmod, p_cmod, p_ws, p_Wsum,
                                     1.0f, p_part, 0);
    sgemm_kernel<3><<<g1, 256>>>(p_v, W, p_t, nullptr, nullptr,
                                 B, 256, 256, 0u, 0u, 0u);
    fe_reduce_kernel<<<B / 8, 256>>>(p_t, p_v, p_bmod, p_cmod, p_ws, p_Wsum,
                                     -1.0f, p_part, B / 8);

    final_reduce_kernel<<<1, 256>>>(p_part, 2 * (B / 8), 1.0f / (float)B, (float*)d_out);
}

// round 7
// speedup vs baseline: 1.0391x; 1.0391x over previous
#include <cuda_runtime.h>
#include <cstdint>
#include <cstddef>

#define BMAX 32768

// ---------------- device scratch (uninitialized globals; no allocations) ----------------
__device__ float g_x[BMAX * 64];              // tanh features of cond MLP
__device__ float g_cond[3 * BMAX * 256];      // [0]=b_mod, [1]=c_mod, [2]=w_scale
__device__ float g_v[BMAX * 256];             // model visible state (0/1 floats)
__device__ float g_h[BMAX * 256];             // h * w_scale
__device__ float g_t[BMAX * 256];             // v @ W scratch for free energy
__device__ float g_WT[256 * 256];             // W transposed: WT[k*256+c] = W[c*256+k]
__device__ float g_P[64 * 768];               // combined cond-param weights, [k][n]
__device__ float g_pb[768];                   // combined cond-param bias
__device__ float g_Wsum[256];                 // W.sum(axis=0)
__device__ float g_part[BMAX / 4];            // block partial sums (2 * B/8)

// ---------------- packed f32x2 FMA (Blackwell; ptxas never auto-fuses) ----------------
#define FFMA2_(d, a, b) \
    asm("fma.rn.f32x2 %0, %1, %2, %0;" : "+l"(d) : "l"(a), "l"(b))
#define PACK2_DUP_(d, s) \
    asm("mov.b64 %0, {%1, %1};" : "=l"(d) : "f"(s))
#define UNPACK2_(lo, hi, s) \
    asm("mov.b64 {%0, %1}, %2;" : "=f"(lo), "=f"(hi) : "l"(s))

// ---------------- threefry2x32-20 (exact JAX PRNG) ----------------
__host__ __device__ inline uint32_t rotl32(uint32_t v, int d) {
    return (v << d) | (v >> (32 - d));
}

__host__ __device__ inline void tf2x32(uint32_t k0, uint32_t k1, uint32_t& x0, uint32_t& x1) {
    uint32_t ks2 = k0 ^ k1 ^ 0x1BD11BDAu;
    x0 += k0; x1 += k1;
    x0 += x1; x1 = rotl32(x1, 13); x1 ^= x0;
    x0 += x1; x1 = rotl32(x1, 15); x1 ^= x0;
    x0 += x1; x1 = rotl32(x1, 26); x1 ^= x0;
    x0 += x1; x1 = rotl32(x1,  6); x1 ^= x0;
    x0 += k1;  x1 += ks2 + 1u;
    x0 += x1; x1 = rotl32(x1, 17); x1 ^= x0;
    x0 += x1; x1 = rotl32(x1, 29); x1 ^= x0;
    x0 += x1; x1 = rotl32(x1, 16); x1 ^= x0;
    x0 += x1; x1 = rotl32(x1, 24); x1 ^= x0;
    x0 += ks2; x1 += k0 + 2u;
    x0 += x1; x1 = rotl32(x1, 13); x1 ^= x0;
    x0 += x1; x1 = rotl32(x1, 15); x1 ^= x0;
    x0 += x1; x1 = rotl32(x1, 26); x1 ^= x0;
    x0 += x1; x1 = rotl32(x1,  6); x1 ^= x0;
    x0 += k0;  x1 += k1 + 3u;
    x0 += x1; x1 = rotl32(x1, 17); x1 ^= x0;
    x0 += x1; x1 = rotl32(x1, 29); x1 ^= x0;
    x0 += x1; x1 = rotl32(x1, 16); x1 ^= x0;
    x0 += x1; x1 = rotl32(x1, 24); x1 ^= x0;
    x0 += k1;  x1 += ks2 + 4u;
    x0 += x1; x1 = rotl32(x1, 13); x1 ^= x0;
    x0 += x1; x1 = rotl32(x1, 15); x1 ^= x0;
    x0 += x1; x1 = rotl32(x1, 26); x1 ^= x0;
    x0 += x1; x1 = rotl32(x1,  6); x1 ^= x0;
    x0 += ks2; x1 += k0 + 5u;
}

// JAX uniform at flat index f of an array with n=2*half elements:
// lane i in [0,half) ciphers counts (i, i+half); flat[i]=out0, flat[i+half]=out1.
__device__ inline float tf_uniform(uint32_t k0, uint32_t k1, uint32_t f, uint32_t half) {
    uint32_t sec = (f >= half) ? 1u : 0u;
    uint32_t lane = sec ? (f - half) : f;
    uint32_t x0 = lane, x1 = lane + half;
    tf2x32(k0, k1, x0, x1);
    uint32_t bits = sec ? x1 : x0;
    return __uint_as_float((bits >> 9) | 0x3f800000u) - 1.0f;
}

__device__ inline float sigmoidf_(float x) {
    float e = expf(-fabsf(x));
    float s = 1.0f / (1.0f + e);
    return (x >= 0.0f) ? s : (1.0f - s);
}

__device__ inline float softplusf_(float x) {
    return fmaxf(x, 0.0f) + log1pf(expf(-fabsf(x)));
}

// ---------------- prep: WT, Wsum, combined cond-param weights ----------------
__global__ void __launch_bounds__(256) prep_kernel(
    const float* __restrict__ W, const float* __restrict__ b, const float* __restrict__ c,
    const float* __restrict__ fc2w, const float* __restrict__ fc2b,
    float* __restrict__ WT, float* __restrict__ P, float* __restrict__ pb,
    float* __restrict__ Wsum)
{
    int idx = blockIdx.x * blockDim.x + threadIdx.x;
    int stride = gridDim.x * blockDim.x;
    for (int i = idx; i < 256 * 256; i += stride) {
        int k = i >> 8, cc = i & 255;
        WT[k * 256 + cc] = W[cc * 256 + k];
    }
    for (int i = idx; i < 64 * 768; i += stride) {
        int k = i / 768, n = i % 768;
        float val;
        if (n < 256)      val = b[n] * fc2w[n * 64 + k] + fc2w[(256 + n) * 64 + k];
        else if (n < 512) { int j = n - 256; val = c[j] * fc2w[(512 + j) * 64 + k] + fc2w[(768 + j) * 64 + k]; }
        else              { int j = n - 512; val = fc2w[(1024 + j) * 64 + k]; }
        P[k * 768 + n] = val;
    }
    for (int i = idx; i < 768; i += stride) {
        float val;
        if (i < 256)      val = b[i] * (1.0f + fc2b[i]) + fc2b[256 + i];
        else if (i < 512) { int j = i - 256; val = c[j] * (1.0f + fc2b[512 + j]) + fc2b[768 + j]; }
        else              { int j = i - 512; val = fc2b[1024 + j]; }
        pb[i] = val;
    }
    for (int i = idx; i < 256; i += stride) {
        float s = 0.0f;
        for (int rr = 0; rr < 256; rr++) s += W[rr * 256 + i];
        Wsum[i] = s;
    }
}

// ---------------- x = tanh(cond @ fc1_w.T + fc1_b), [B,64]x[64,64] ----------------
__global__ void __launch_bounds__(256) cond_fc1_kernel(
    const float* __restrict__ cond, const float* __restrict__ fc1w,
    const float* __restrict__ fc1b, float* __restrict__ xout)
{
    __shared__ float Cs[64][65];
    __shared__ float Ws[64][65];   // Ws[k][j] = fc1w[j*64+k]
    int t = threadIdx.x;
    int r0 = blockIdx.x * 64;
#pragma unroll
    for (int l = 0; l < 4; l++) {
        int id = t + l * 256;
        int j = id >> 4, k4 = (id & 15) << 2;
        float4 w = *(const float4*)(fc1w + j * 64 + k4);
        Ws[k4 + 0][j] = w.x; Ws[k4 + 1][j] = w.y; Ws[k4 + 2][j] = w.z; Ws[k4 + 3][j] = w.w;
    }
#pragma unroll
    for (int l = 0; l < 4; l++) {
        int id = t + l * 256;
        int i = id >> 4, k4 = (id & 15) << 2;
        float4 v = *(const float4*)(cond + (size_t)(r0 + i) * 64 + k4);
        Cs[i][k4 + 0] = v.x; Cs[i][k4 + 1] = v.y; Cs[i][k4 + 2] = v.z; Cs[i][k4 + 3] = v.w;
    }
    __syncthreads();
    int tx = t & 15, ty = t >> 4;
    float acc[4][4];
#pragma unroll
    for (int i = 0; i < 4; i++)
#pragma unroll
        for (int j = 0; j < 4; j++) acc[i][j] = 0.0f;
#pragma unroll 8
    for (int k = 0; k < 64; k++) {
        float a[4], bv[4];
#pragma unroll
        for (int i = 0; i < 4; i++) a[i] = Cs[ty * 4 + i][k];
#pragma unroll
        for (int j = 0; j < 4; j++) bv[j] = Ws[k][tx * 4 + j];
#pragma unroll
        for (int i = 0; i < 4; i++)
#pragma unroll
            for (int j = 0; j < 4; j++) acc[i][j] = fmaf(a[i], bv[j], acc[i][j]);
    }
#pragma unroll
    for (int i = 0; i < 4; i++) {
        int r = r0 + ty * 4 + i;
#pragma unroll
        for (int j = 0; j < 4; j++) {
            int jj = tx * 4 + j;
            xout[(size_t)r * 64 + jj] = tanhf(acc[i][j] + fc1b[jj]);
        }
    }
}

// ---------------- v_model init: noise rows (threefry) + copy of v_data ----------------
__global__ void __launch_bounds__(256) init_v_kernel(
    const float* __restrict__ vdata, float* __restrict__ v,
    int B, int n_noise, uint32_t k0, uint32_t k1)
{
    int total = B * 256;
    uint32_t half = (uint32_t)(n_noise * 128);
    for (int idx = blockIdx.x * blockDim.x + threadIdx.x; idx < total;
         idx += gridDim.x * blockDim.x) {
        int r = idx >> 8;
        float val;
        if (r < n_noise) {
            float u = tf_uniform(k0, k1, (uint32_t)idx, half);
            val = (u < 0.5f) ? 1.0f : 0.0f;
        } else {
            val = vdata[idx];
        }
        v[idx] = val;
    }
}

// ---------------- 128x128x16 SGEMM, packed f32x2, fused epilogues ----------------
// Row pairs packed in f32x2 lanes; columns per thread are tx + 16*j (conflict-free Bs).
// MODE 0: cond params; MODE 1: h-sample (stores h*w_scale); MODE 2: v-sample;
// MODE 3: plain store.
template <int MODE>
__global__ void __launch_bounds__(256, 2) sgemm_kernel(
    const float* __restrict__ A, const float* __restrict__ Bm,
    float* __restrict__ out,
    const float* __restrict__ e0, const float* __restrict__ e1,
    int M, int N, int K,
    uint32_t rk0, uint32_t rk1, uint32_t half)
{
    __shared__ float As[16][136];   // [k][row], padded even for 64-bit row-pair loads
    __shared__ float Bs[16][128];   // [k][n]
    const int t = threadIdx.x;
    const int tx = t & 15, ty = t >> 4;
    const int bx = blockIdx.x, by = blockIdx.y;
    const float* Ab = A + (size_t)by * 128 * K;
    const float* Bb = Bm + (size_t)bx * 128;

    unsigned long long acc2[4][8];  // [row-pair][col], f32x2 packed
#pragma unroll
    for (int i = 0; i < 4; i++)
#pragma unroll
        for (int j = 0; j < 8; j++) acc2[i][j] = 0ull;

    // prefetch registers for tile kb=0
    float4 ra[2], rb[2];
    {
#pragma unroll
        for (int l = 0; l < 2; l++) {
            int id = t + l * 256;
            int row = id >> 2, c4 = (id & 3) << 2;
            ra[l] = *(const float4*)(Ab + (size_t)row * K + c4);
        }
#pragma unroll
        for (int l = 0; l < 2; l++) {
            int id = t + l * 256;
            int kk = id >> 5, n4 = (id & 31) << 2;
            rb[l] = *(const float4*)(Bb + (size_t)kk * N + n4);
        }
    }

    for (int kb = 0; kb < K; kb += 16) {
        // stage current tile into smem
#pragma unroll
        for (int l = 0; l < 2; l++) {
            int id = t + l * 256;
            int row = id >> 2, c4 = (id & 3) << 2;
            As[c4 + 0][row] = ra[l].x; As[c4 + 1][row] = ra[l].y;
            As[c4 + 2][row] = ra[l].z; As[c4 + 3][row] = ra[l].w;
        }
#pragma unroll
        for (int l = 0; l < 2; l++) {
            int id = t + l * 256;
            int kk = id >> 5, n4 = (id & 31) << 2;
            *(float4*)&Bs[kk][n4] = rb[l];
        }
        __syncthreads();

        // prefetch next tile (overlaps with compute)
        if (kb + 16 < K) {
#pragma unroll
            for (int l = 0; l < 2; l++) {
                int id = t + l * 256;
                int row = id >> 2, c4 = (id & 3) << 2;
                ra[l] = *(const float4*)(Ab + (size_t)row * K + kb + 16 + c4);
            }
#pragma unroll
            for (int l = 0; l < 2; l++) {
                int id = t + l * 256;
                int kk = id >> 5, n4 = (id & 31) << 2;
                rb[l] = *(const float4*)(Bb + (size_t)(kb + 16 + kk) * N + n4);
            }
        }

#pragma unroll
        for (int kk = 0; kk < 16; kk++) {
            unsigned long long a2[4];
#pragma unroll
            for (int i = 0; i < 4; i++)
                a2[i] = *(const unsigned long long*)&As[kk][ty * 8 + i * 2];
#pragma unroll
            for (int j = 0; j < 8; j++) {
                float bj = Bs[kk][tx + 16 * j];
                unsigned long long b2;
                PACK2_DUP_(b2, bj);
#pragma unroll
                for (int i = 0; i < 4; i++)
                    FFMA2_(acc2[i][j], a2[i], b2);
            }
        }
        __syncthreads();
    }

#pragma unroll
    for (int i = 0; i < 4; i++) {
        int r0 = by * 128 + ty * 8 + i * 2;
#pragma unroll
        for (int j = 0; j < 8; j++) {
            int c = bx * 128 + tx + 16 * j;
            float vlo, vhi;
            UNPACK2_(vlo, vhi, acc2[i][j]);
#pragma unroll
            for (int p = 0; p < 2; p++) {
                int r = r0 + p;
                float v = p ? vhi : vlo;
                if (MODE == 0) {
                    float val = v + e0[c];
                    if (c >= 512) val = 1.0f + 0.05f * tanhf(val);
                    size_t idx = (size_t)(c >> 8) * M * 256 + (size_t)r * 256 + (c & 255);
                    out[idx] = val;
                } else if (MODE == 1) {
                    size_t idx = (size_t)r * 256 + c;
                    float ws = e0[idx];
                    float pp = sigmoidf_(fmaf(v, ws, e1[idx]));
                    float u = tf_uniform(rk0, rk1, (uint32_t)idx, half);
                    out[idx] = (u < pp) ? ws : 0.0f;
                } else if (MODE == 2) {
                    size_t idx = (size_t)r * 256 + c;
                    float pp = sigmoidf_(v + e0[idx]);
                    float u = tf_uniform(rk0, rk1, (uint32_t)idx, half);
                    out[idx] = (u < pp) ? 1.0f : 0.0f;
                } else {
                    out[(size_t)r * 256 + c] = v;
                }
            }
        }
    }
}

// ---------------- free-energy row reduce (deterministic) ----------------
__global__ void __launch_bounds__(256) fe_reduce_kernel(
    const float* __restrict__ vw, const float* __restrict__ v,
    const float* __restrict__ bmod, const float* __restrict__ cmod,
    const float* __restrict__ ws, const float* __restrict__ Wsum,
    float sign, float* __restrict__ part, int partBase)
{
    __shared__ float sW[256];
    __shared__ float wres[8];
    int t = threadIdx.x;
    sW[t] = Wsum[t];
    __syncthreads();
    int warp = t >> 5, lane = t & 31;
    int r = blockIdx.x * 8 + warp;
    size_t base = (size_t)r * 256;
    float s2v = 0.0f, s2f = 0.0f, s1v = 0.0f, s1f = 0.0f;
#pragma unroll
    for (int jj = 0; jj < 8; jj++) {
        int c = jj * 32 + lane;
        float tt = vw[base + c];
        float w  = ws[base + c];
        float cm = cmod[base + c];
        float tv = tt * w;
        float lv = tv + cm;
        float lf = fmaf(sW[c], w, cm) - tv;
        s2v += softplusf_(lv);
        s2f += softplusf_(lf);
        float bm = bmod[base + c];
        float vv = v[base + c];
        s1v = fmaf(vv, bm, s1v);
        s1f = fmaf(1.0f - vv, bm, s1f);
    }
#pragma unroll
    for (int o = 16; o > 0; o >>= 1) {
        s2v += __shfl_xor_sync(0xffffffffu, s2v, o);
        s2f += __shfl_xor_sync(0xffffffffu, s2f, o);
        s1v += __shfl_xor_sync(0xffffffffu, s1v, o);
        s1f += __shfl_xor_sync(0xffffffffu, s1f, o);
    }
    if (lane == 0) {
        float av = s1v + s2v;       // = -fe_v
        float af = s1f + s2f;       // = -fe_f
        float mx = fmaxf(av, af);
        float fe = -(mx + log1pf(expf(-fabsf(av - af))));
        wres[warp] = sign * fe;
    }
    __syncthreads();
    if (t == 0) {
        float s = 0.0f;
#pragma unroll
        for (int w = 0; w < 8; w++) s += wres[w];
        part[partBase + blockIdx.x] = s;
    }
}

__global__ void __launch_bounds__(256) final_reduce_kernel(
    const float* __restrict__ part, int n, float invB, float* __restrict__ out)
{
    __shared__ float s[256];
    float acc = 0.0f;
    for (int i = threadIdx.x; i < n; i += 256) acc += part[i];
    s[threadIdx.x] = acc;
    __syncthreads();
    for (int o = 128; o > 0; o >>= 1) {
        if (threadIdx.x < o) s[threadIdx.x] += s[threadIdx.x + o];
        __syncthreads();
    }
    if (threadIdx.x == 0) out[0] = s[0] * invB;
}

// ---------------- host: JAX key chain ----------------
static inline void host_split2(uint32_t k0, uint32_t k1, uint32_t* ka, uint32_t* kb) {
    uint32_t a0 = 0, b0 = 2; tf2x32(k0, k1, a0, b0);
    uint32_t a1 = 1, b1 = 3; tf2x32(k0, k1, a1, b1);
    ka[0] = a0; ka[1] = a1; kb[0] = b0; kb[1] = b1;
}
static inline void host_split3(uint32_t k0, uint32_t k1,
                               uint32_t* kA, uint32_t* kB, uint32_t* kC) {
    uint32_t a0 = 0, b0 = 3; tf2x32(k0, k1, a0, b0);
    uint32_t a1 = 1, b1 = 4; tf2x32(k0, k1, a1, b1);
    uint32_t a2 = 2, b2 = 5; tf2x32(k0, k1, a2, b2);
    kA[0] = a0; kA[1] = a1;
    kB[0] = a2; kB[1] = b0;
    kC[0] = b1; kC[1] = b2;
}

extern "C" void kernel_launch(void* const* d_in, const int* in_sizes, int n_in,
                              void* d_out, int out_size)
{
    const float* v_data = (const float*)d_in[0];
    const float* cond   = (const float*)d_in[1];
    const float* W      = (const float*)d_in[2];
    const float* b      = (const float*)d_in[3];
    const float* c      = (const float*)d_in[4];
    const float* fc1w   = (const float*)d_in[5];
    const float* fc1b   = (const float*)d_in[6];
    const float* fc2w   = (const float*)d_in[7];
    const float* fc2b   = (const float*)d_in[8];

    int B = in_sizes[0] / 256;
    if (B > BMAX) B = BMAX;
    int n_noise = (int)((double)B * 0.1);   // int(B*0.1) => 3276 for B=32768

    float *p_x, *p_cond, *p_v, *p_h, *p_t, *p_WT, *p_P, *p_pb, *p_Wsum, *p_part;
    cudaGetSymbolAddress((void**)&p_x,    g_x);
    cudaGetSymbolAddress((void**)&p_cond, g_cond);
    cudaGetSymbolAddress((void**)&p_v,    g_v);
    cudaGetSymbolAddress((void**)&p_h,    g_h);
    cudaGetSymbolAddress((void**)&p_t,    g_t);
    cudaGetSymbolAddress((void**)&p_WT,   g_WT);
    cudaGetSymbolAddress((void**)&p_P,    g_P);
    cudaGetSymbolAddress((void**)&p_pb,   g_pb);
    cudaGetSymbolAddress((void**)&p_Wsum, g_Wsum);
    cudaGetSymbolAddress((void**)&p_part, g_part);
    float* p_bmod = p_cond;
    float* p_cmod = p_cond + (size_t)B * 256;
    float* p_ws   = p_cond + (size_t)2 * B * 256;

    // JAX key chain: key(42) -> split(2) -> 5x split(3)
    uint32_t rng[2] = {0u, 42u};
    uint32_t kn[2];
    host_split2(rng[0], rng[1], rng, kn);
    uint32_t k1s[5][2], k2s[5][2];
    for (int s = 0; s < 5; s++) {
        uint32_t nk[2];
        host_split3(rng[0], rng[1], nk, k1s[s], k2s[s]);
        rng[0] = nk[0]; rng[1] = nk[1];
    }

    prep_kernel<<<128, 256>>>(W, b, c, fc2w, fc2b, p_WT, p_P, p_pb, p_Wsum);
    cond_fc1_kernel<<<B / 64, 256>>>(cond, fc1w, fc1b, p_x);

    dim3 g0(6, B / 128);
    sgemm_kernel<0><<<g0, 256>>>(p_x, p_P, p_cond, p_pb, nullptr,
                                 B, 768, 64, 0u, 0u, 0u);

    init_v_kernel<<<2048, 256>>>(v_data, p_v, B, n_noise, kn[0], kn[1]);

    uint32_t half = (uint32_t)B * 128u;
    dim3 g1(2, B / 128);
    for (int s = 0; s < 5; s++) {
        sgemm_kernel<1><<<g1, 256>>>(p_v, W, p_h, p_ws, p_cmod,
                                     B, 256, 256, k1s[s][0], k1s[s][1], half);
        sgemm_kernel<2><<<g1, 256>>>(p_h, p_WT, p_v, p_bmod, nullptr,
                                     B, 256, 256, k2s[s][0], k2s[s][1], half);
    }

    // free energy: data (+) and model (-)
    sgemm_kernel<3><<<g1, 256>>>(v_data, W, p_t, nullptr, nullptr,
                                 B, 256, 256, 0u, 0u, 0u);
    fe_reduce_kernel<<<B / 8, 256>>>(p_t, v_data, p_bmod, p_cmod, p_ws, p_Wsum,
                                     1.0f, p_part, 0);
    sgemm_kernel<3><<<g1, 256>>>(p_v, W, p_t, nullptr, nullptr,
                                 B, 256, 256, 0u, 0u, 0u);
    fe_reduce_kernel<<<B / 8, 256>>>(p_t, p_v, p_bmod, p_cmod, p_ws, p_Wsum,
                                     -1.0f, p_part, B / 8);

    final_reduce_kernel<<<1, 256>>>(p_part, 2 * (B / 8), 1.0f / (float)B, (float*)d_out);
}